// round 2
// baseline (speedup 1.0000x reference)
#include <cuda_runtime.h>
#include <math.h>

#define NHEADS 16
#define HDIM   64
#define SEQ    2048
#define BATCH  2
#define HID    1024
#define NTOK   (BATCH*SEQ)      // 4096

// ---------------- scratch (device globals: allocation-free) ----------------
__device__ float g_q[BATCH*NHEADS*SEQ*HDIM];   // [b][h][s][d]
__device__ float g_k[BATCH*NHEADS*SEQ*HDIM];
__device__ float g_v[BATCH*NHEADS*SEQ*HDIM];
__device__ float g_attn[(size_t)NTOK*HID];     // [t][o]  (o = h*64+d)
__device__ float g_cos[SEQ*32];
__device__ float g_sin[SEQ*32];

// ---------------- RoPE table: double sincos (fast-math-proof) --------------
__global__ void rope_table_kernel() {
    int idx = blockIdx.x * blockDim.x + threadIdx.x;
    if (idx >= SEQ*32) return;
    int s = idx >> 5, i = idx & 31;
    double invd = pow(10000.0, -((double)i) / 32.0);
    float ang = (float)s * (float)invd;
    double sv, cv;
    sincos((double)ang, &sv, &cv);
    g_cos[idx] = (float)cv;
    g_sin[idx] = (float)sv;
}

// ---------------- NT GEMM: C[M,N] = A[M,K] * W[N,K]^T ----------------------
// M=4096, N=1024, K=1024. 128x128x8 tiles, 256 threads, 8x8 micro-tile.
// dest_sel: 0/1/2 -> g_q/g_k/g_v in [b][h][s][d] layout; 3 -> outp [row][col].
// A==nullptr -> read from g_attn.
__global__ void __launch_bounds__(256) gemm_nt_kernel(
    const float* __restrict__ A, const float* __restrict__ W,
    float* __restrict__ outp, int dest_sel)
{
    __shared__ __align__(16) float As[8][128];
    __shared__ __align__(16) float Bs[8][128];
    if (A == nullptr) A = g_attn;
    float* dst;
    if      (dest_sel == 0) dst = g_q;
    else if (dest_sel == 1) dst = g_k;
    else if (dest_sel == 2) dst = g_v;
    else                    dst = outp;

    int tid = threadIdx.x;
    int tx = tid & 15, ty = tid >> 4;
    int m0 = blockIdx.y << 7, n0 = blockIdx.x << 7;

    float acc[8][8];
#pragma unroll
    for (int i = 0; i < 8; i++)
#pragma unroll
        for (int j = 0; j < 8; j++) acc[i][j] = 0.f;

    int lrow = tid >> 1;            // 0..127
    int lk   = (tid & 1) << 2;      // 0 or 4
    const float* Ap = A + (size_t)(m0 + lrow) * HID + lk;
    const float* Wp = W + (size_t)(n0 + lrow) * HID + lk;

    for (int k0 = 0; k0 < HID; k0 += 8) {
        float4 av = *(const float4*)(Ap + k0);
        float4 wv = *(const float4*)(Wp + k0);
        As[lk+0][lrow] = av.x; As[lk+1][lrow] = av.y;
        As[lk+2][lrow] = av.z; As[lk+3][lrow] = av.w;
        Bs[lk+0][lrow] = wv.x; Bs[lk+1][lrow] = wv.y;
        Bs[lk+2][lrow] = wv.z; Bs[lk+3][lrow] = wv.w;
        __syncthreads();
#pragma unroll
        for (int kk = 0; kk < 8; kk++) {
            float a[8], b[8];
            *(float4*)(a)   = *(const float4*)(&As[kk][(ty<<3)]);
            *(float4*)(a+4) = *(const float4*)(&As[kk][(ty<<3)+4]);
            *(float4*)(b)   = *(const float4*)(&Bs[kk][(tx<<3)]);
            *(float4*)(b+4) = *(const float4*)(&Bs[kk][(tx<<3)+4]);
#pragma unroll
            for (int i = 0; i < 8; i++)
#pragma unroll
                for (int j = 0; j < 8; j++)
                    acc[i][j] = fmaf(a[i], b[j], acc[i][j]);
        }
        __syncthreads();
    }

    if (dest_sel < 3) {
#pragma unroll
        for (int i = 0; i < 8; i++) {
            int row = m0 + (ty<<3) + i;
            int b = row >> 11, s = row & (SEQ-1);
#pragma unroll
            for (int jq = 0; jq < 2; jq++) {
                int col = n0 + (tx<<3) + (jq<<2);
                int h = col >> 6, d = col & 63;      // quad never crosses a head
                float4 v = make_float4(acc[i][(jq<<2)+0], acc[i][(jq<<2)+1],
                                       acc[i][(jq<<2)+2], acc[i][(jq<<2)+3]);
                *(float4*)(&dst[(((size_t)(b<<4) + h) * SEQ + s) * HDIM + d]) = v;
            }
        }
    } else {
#pragma unroll
        for (int i = 0; i < 8; i++) {
            int row = m0 + (ty<<3) + i;
#pragma unroll
            for (int jq = 0; jq < 2; jq++) {
                int col = n0 + (tx<<3) + (jq<<2);
                float4 v = make_float4(acc[i][(jq<<2)+0], acc[i][(jq<<2)+1],
                                       acc[i][(jq<<2)+2], acc[i][(jq<<2)+3]);
                *(float4*)(&dst[(size_t)row * HID + col]) = v;
            }
        }
    }
}

// ---------------- RoPE apply (in place on [b][h][s][d]) --------------------
__global__ void rope_apply_kernel(int which) {
    float* buf = which ? g_k : g_q;
    int idx = blockIdx.x * blockDim.x + threadIdx.x;   // one (row, pair)
    if (idx >= BATCH*NHEADS*SEQ*32) return;
    int d2 = idx & 31;
    int s  = (idx >> 5) & (SEQ-1);
    size_t base = ((size_t)(idx >> 5)) * HDIM + (d2 << 1);
    float c  = g_cos[(s<<5) + d2];
    float sn = g_sin[(s<<5) + d2];
    float2 xv = *(float2*)(buf + base);
    float2 ov;
    ov.x = xv.x * c - xv.y * sn;
    ov.y = xv.x * sn + xv.y * c;
    *(float2*)(buf + base) = ov;
}

// ---------------- Flash attention (fp32, BQ=BK=128) ------------------------
#define FBQ 128
#define FBK 128
#define FLASH_SMEM_FLOATS (64*128 + 64*128 + 128*64 + 128*128)
#define FLASH_SMEM_BYTES  (FLASH_SMEM_FLOATS * 4)   // 163840 B

__global__ void __launch_bounds__(256) flash_kernel() {
    extern __shared__ float sm[];
    float* Qs = sm;                 // [64][128]  d-major, swizzled, pre-scaled
    float* Ks = Qs + 64*128;        // [64][128]  d-major, swizzled
    float* Vs = Ks + 64*128;        // [128][64]  k-major (row-major V)
    float* Ps = Vs + 128*64;        // [128][128] c-major (k index), swizzled
    int tid = threadIdx.x;
    int tx = tid & 15, ty = tid >> 4;
    int bh = blockIdx.y;                       // b*16 + h
    int q0 = blockIdx.x * FBQ;
    const float* Qp = g_q + (size_t)bh * SEQ * HDIM;
    const float* Kp = g_k + (size_t)bh * SEQ * HDIM;
    const float* Vp = g_v + (size_t)bh * SEQ * HDIM;
    float* out = g_attn;

    int lc = tid & 15;          // d-group: d4 = lc*4
    int lr = tid >> 4;          // 0..15
    int d4 = lc << 2;
    int swz_st = lc << 3;       // ((d>>2)&15)<<3 for d in [d4, d4+3]

    // load Q tile (transposed to d-major, swizzled columns, scaled by 1/sqrt(64))
#pragma unroll
    for (int rr = 0; rr < 8; rr++) {
        int row = (rr << 4) + lr;
        float4 v = *(const float4*)(Qp + (size_t)(q0 + row) * HDIM + d4);
        int pr = row ^ swz_st;
        Qs[(d4+0)*128 + pr] = v.x * 0.125f;
        Qs[(d4+1)*128 + pr] = v.y * 0.125f;
        Qs[(d4+2)*128 + pr] = v.z * 0.125f;
        Qs[(d4+3)*128 + pr] = v.w * 0.125f;
    }

    float m[8], l[8], o[8][4];
#pragma unroll
    for (int i = 0; i < 8; i++) {
        m[i] = -INFINITY; l[i] = 0.f;
#pragma unroll
        for (int j = 0; j < 4; j++) o[i][j] = 0.f;
    }

    for (int k0 = 0; k0 < SEQ; k0 += FBK) {
        // load K (transposed+swizzled) and V (row-major)
#pragma unroll
        for (int rr = 0; rr < 8; rr++) {
            int row = (rr << 4) + lr;
            float4 kv = *(const float4*)(Kp + (size_t)(k0 + row) * HDIM + d4);
            int pr = row ^ swz_st;
            Ks[(d4+0)*128 + pr] = kv.x;
            Ks[(d4+1)*128 + pr] = kv.y;
            Ks[(d4+2)*128 + pr] = kv.z;
            Ks[(d4+3)*128 + pr] = kv.w;
            float4 vv = *(const float4*)(Vp + (size_t)(k0 + row) * HDIM + d4);
            *(float4*)(&Vs[row*64 + d4]) = vv;
        }
        __syncthreads();

        // scores: S = Q*K^T  (rows ty*8+i, cols tx*8+j)
        float acc[8][8];
#pragma unroll
        for (int i = 0; i < 8; i++)
#pragma unroll
            for (int j = 0; j < 8; j++) acc[i][j] = 0.f;
#pragma unroll 4
        for (int kk = 0; kk < 64; kk++) {
            int swz = ((kk >> 2) & 15) << 3;
            float a[8], b[8];
            int ab = (ty << 3) ^ swz;
            int bb = (tx << 3) ^ swz;
            *(float4*)(a)   = *(const float4*)(&Qs[kk*128 + ab]);
            *(float4*)(a+4) = *(const float4*)(&Qs[kk*128 + ab + 4]);
            *(float4*)(b)   = *(const float4*)(&Ks[kk*128 + bb]);
            *(float4*)(b+4) = *(const float4*)(&Ks[kk*128 + bb + 4]);
#pragma unroll
            for (int i = 0; i < 8; i++)
#pragma unroll
                for (int j = 0; j < 8; j++)
                    acc[i][j] = fmaf(a[i], b[j], acc[i][j]);
        }

        // online softmax (row groups = 16 consecutive lanes -> shfl width 16)
#pragma unroll
        for (int i = 0; i < 8; i++) {
            float v = acc[i][0];
#pragma unroll
            for (int j = 1; j < 8; j++) v = fmaxf(v, acc[i][j]);
#pragma unroll
            for (int off = 8; off >= 1; off >>= 1)
                v = fmaxf(v, __shfl_xor_sync(0xffffffffu, v, off, 16));
            float mn = fmaxf(m[i], v);
            float corr = __expf(m[i] - mn);
            m[i] = mn;
            float rs = 0.f;
#pragma unroll
            for (int j = 0; j < 8; j++) {
                float p = __expf(acc[i][j] - mn);
                acc[i][j] = p;
                rs += p;
            }
#pragma unroll
            for (int off = 8; off >= 1; off >>= 1)
                rs += __shfl_xor_sync(0xffffffffu, rs, off, 16);
            l[i] = l[i] * corr + rs;
#pragma unroll
            for (int j = 0; j < 4; j++) o[i][j] *= corr;
        }

        // store P as [c][r] with row swizzle  (phys r = r ^ ((c>>3)<<3))
        {
            int rb = (ty << 3) ^ (tx << 3);
#pragma unroll
            for (int j = 0; j < 8; j++) {
                int c = (tx << 3) + j;
                float4 p0 = make_float4(acc[0][j], acc[1][j], acc[2][j], acc[3][j]);
                float4 p1 = make_float4(acc[4][j], acc[5][j], acc[6][j], acc[7][j]);
                *(float4*)(&Ps[c*128 + rb])     = p0;
                *(float4*)(&Ps[c*128 + rb + 4]) = p1;
            }
        }
        __syncthreads();

        // O += P * V   (rows ty*8+i, d-cols tx*4+j)
#pragma unroll 4
        for (int kk = 0; kk < FBK; kk++) {
            int swz = ((kk >> 3) & 15) << 3;
            float a[8], b[4];
            int ab = (ty << 3) ^ swz;
            *(float4*)(a)   = *(const float4*)(&Ps[kk*128 + ab]);
            *(float4*)(a+4) = *(const float4*)(&Ps[kk*128 + ab + 4]);
            *(float4*)(b)   = *(const float4*)(&Vs[kk*64 + (tx<<2)]);
#pragma unroll
            for (int i = 0; i < 8; i++)
#pragma unroll
                for (int j = 0; j < 4; j++)
                    o[i][j] = fmaf(a[i], b[j], o[i][j]);
        }
        __syncthreads();   // protect Ks/Vs/Ps before next tile's loads
    }

    // epilogue: normalize and write [t][o] layout for the output projection
    int b = bh >> 4, h = bh & 15;
#pragma unroll
    for (int i = 0; i < 8; i++) {
        int r = q0 + (ty << 3) + i;
        float inv = 1.0f / l[i];
        float4 ov = make_float4(o[i][0]*inv, o[i][1]*inv, o[i][2]*inv, o[i][3]*inv);
        *(float4*)(&out[((size_t)b * SEQ + r) * HID + (h << 6) + (tx << 2)]) = ov;
    }
}

// ---------------- launch ----------------------------------------------------
extern "C" void kernel_launch(void* const* d_in, const int* in_sizes, int n_in,
                              void* d_out, int out_size) {
    const float* x  = (const float*)d_in[0];
    const float* wq = (const float*)d_in[1];
    const float* wk = (const float*)d_in[2];
    const float* wv = (const float*)d_in[3];
    const float* wo = (const float*)d_in[4];
    float* out = (float*)d_out;

    rope_table_kernel<<<(SEQ*32 + 255)/256, 256>>>();

    dim3 gg(HID/128, NTOK/128);                 // (8, 32)
    gemm_nt_kernel<<<gg, 256>>>(x, wq, nullptr, 0);
    gemm_nt_kernel<<<gg, 256>>>(x, wk, nullptr, 1);
    gemm_nt_kernel<<<gg, 256>>>(x, wv, nullptr, 2);

    int npairs = BATCH*NHEADS*SEQ*32;
    rope_apply_kernel<<<npairs/256, 256>>>(0);
    rope_apply_kernel<<<npairs/256, 256>>>(1);

    cudaFuncSetAttribute(flash_kernel,
                         cudaFuncAttributeMaxDynamicSharedMemorySize,
                         FLASH_SMEM_BYTES);
    dim3 fg(SEQ/FBQ, BATCH*NHEADS);             // (16, 32)
    flash_kernel<<<fg, 256, FLASH_SMEM_BYTES>>>();

    gemm_nt_kernel<<<gg, 256>>>(nullptr, wo, out, 3);
}

// round 4
// speedup vs baseline: 1.9570x; 1.9570x over previous
#include <cuda_runtime.h>
#include <cuda_bf16.h>
#include <math.h>
#include <stdint.h>

#define NHEADS 16
#define HDIM   64
#define SEQ    2048
#define BATCH  2
#define HID    1024
#define NTOK   (BATCH*SEQ)      // 4096

// ---------------- scratch (device globals: allocation-free) ----------------
__device__ float g_q[BATCH*NHEADS*SEQ*HDIM];   // [b][h][s][d]
__device__ float g_k[BATCH*NHEADS*SEQ*HDIM];
__device__ float g_v[BATCH*NHEADS*SEQ*HDIM];
__device__ float g_attn[(size_t)NTOK*HID];     // [t][h*64+d]
__device__ float g_cos[SEQ*32];
__device__ float g_sin[SEQ*32];

// ---------------- small helpers -------------------------------------------
__device__ __forceinline__ uint32_t pack2(float lo, float hi) {
    __nv_bfloat162 h = __floats2bfloat162_rn(lo, hi);   // .x = lo (low half)
    return *reinterpret_cast<uint32_t*>(&h);
}
__device__ __forceinline__ float bfhi(float x) {
    return __bfloat162float(__float2bfloat16(x));
}
__device__ __forceinline__ void ldsm4(uint32_t addr, uint32_t &r0, uint32_t &r1,
                                      uint32_t &r2, uint32_t &r3) {
    asm volatile("ldmatrix.sync.aligned.m8n8.x4.shared.b16 {%0,%1,%2,%3}, [%4];\n"
                 : "=r"(r0), "=r"(r1), "=r"(r2), "=r"(r3) : "r"(addr));
}
__device__ __forceinline__ void mma16816(float d[4], uint32_t a0, uint32_t a1,
                                         uint32_t a2, uint32_t a3,
                                         uint32_t b0, uint32_t b1) {
    asm volatile("mma.sync.aligned.m16n8k16.row.col.f32.bf16.bf16.f32 "
                 "{%0,%1,%2,%3},{%4,%5,%6,%7},{%8,%9},{%0,%1,%2,%3};\n"
                 : "+f"(d[0]), "+f"(d[1]), "+f"(d[2]), "+f"(d[3])
                 : "r"(a0), "r"(a1), "r"(a2), "r"(a3), "r"(b0), "r"(b1));
}
// ldmatrix.x4 per-lane address: rows row0..row0+15 (lane&15), 16B chunk
// chunk0 + (lane>>4), XOR-swizzled by (row&7). rshift: log2(row bytes).
__device__ __forceinline__ uint32_t laddr(uint32_t base, int row0, int chunk0,
                                          int lane, int rshift) {
    int r = row0 + (lane & 15);
    int c = chunk0 + (lane >> 4);
    return base + (r << rshift) + (((c ^ (r & 7))) << 4);
}
// store float4 as bf16 hi/lo planes; row stride 64 elems (128B), swizzled
__device__ __forceinline__ void store_split64(__nv_bfloat16* ph, __nv_bfloat16* pl,
                                              int r, int kc, float4 v) {
    int eo = r*64 + ((((kc>>3) ^ (r&7)))<<3) + (kc&7);
    float h0 = bfhi(v.x), h1 = bfhi(v.y), h2 = bfhi(v.z), h3 = bfhi(v.w);
    *(__nv_bfloat162*)(ph+eo)   = __floats2bfloat162_rn(v.x, v.y);
    *(__nv_bfloat162*)(ph+eo+2) = __floats2bfloat162_rn(v.z, v.w);
    *(__nv_bfloat162*)(pl+eo)   = __floats2bfloat162_rn(v.x-h0, v.y-h1);
    *(__nv_bfloat162*)(pl+eo+2) = __floats2bfloat162_rn(v.z-h2, v.w-h3);
}

// ---------------- RoPE table: double sincos (fast-math-proof) --------------
__global__ void rope_table_kernel() {
    int idx = blockIdx.x * blockDim.x + threadIdx.x;
    if (idx >= SEQ*32) return;
    int s = idx >> 5, i = idx & 31;
    double invd = pow(10000.0, -((double)i) / 32.0);
    float ang = (float)s * (float)invd;
    double sv, cv;
    sincos((double)ang, &sv, &cv);
    g_cos[idx] = (float)cv;
    g_sin[idx] = (float)sv;
}

// ---------------- RoPE apply (in place on [b][h][s][d]) --------------------
__global__ void rope_apply_kernel(int which) {
    float* buf = which ? g_k : g_q;
    int idx = blockIdx.x * blockDim.x + threadIdx.x;
    if (idx >= BATCH*NHEADS*SEQ*32) return;
    int d2 = idx & 31;
    int s  = (idx >> 5) & (SEQ-1);
    size_t base = ((size_t)(idx >> 5)) * HDIM + (d2 << 1);
    float c  = g_cos[(s<<5) + d2];
    float sn = g_sin[(s<<5) + d2];
    float2 xv = *(float2*)(buf + base);
    float2 ov;
    ov.x = xv.x * c - xv.y * sn;
    ov.y = xv.x * sn + xv.y * c;
    *(float2*)(buf + base) = ov;
}

// ---------------- split-bf16 tensor GEMM: C = A[M,K] * W[N,K]^T ------------
// 128x128 tile, BK=64, 256 threads (8 warps, each: 16 rows x 128 cols).
// dest_sel 0/1/2 -> g_q/g_k/g_v [b][h][s][d]; 3 -> outp [row][col]. A==0 -> g_attn.
#define GEMM_SMEM_BYTES (4*8192*2)   // Ah,Al,Bh,Bl planes of 128x64 bf16 = 64KB

__global__ void __launch_bounds__(256, 1) gemm_mma_kernel(
    const float* __restrict__ A, const float* __restrict__ W,
    float* __restrict__ outp, int dest_sel)
{
    extern __shared__ __nv_bfloat16 smg[];
    __nv_bfloat16 *Ah = smg, *Al = smg + 8192, *Bh = smg + 16384, *Bl = smg + 24576;
    if (A == nullptr) A = g_attn;
    float* dst;
    if      (dest_sel == 0) dst = g_q;
    else if (dest_sel == 1) dst = g_k;
    else if (dest_sel == 2) dst = g_v;
    else                    dst = outp;

    int tid = threadIdx.x, lane = tid & 31, wid = tid >> 5;
    int m0 = blockIdx.y << 7, n0 = blockIdx.x << 7;

    uint32_t uAh = (uint32_t)__cvta_generic_to_shared(Ah);
    uint32_t uAl = (uint32_t)__cvta_generic_to_shared(Al);
    uint32_t uBh = (uint32_t)__cvta_generic_to_shared(Bh);
    uint32_t uBl = (uint32_t)__cvta_generic_to_shared(Bl);

    float acc[16][4];
#pragma unroll
    for (int t = 0; t < 16; t++)
#pragma unroll
        for (int j = 0; j < 4; j++) acc[t][j] = 0.f;

    int rb = tid >> 4, c4 = (tid & 15) << 2;

    for (int k0 = 0; k0 < HID; k0 += 64) {
#pragma unroll
        for (int i = 0; i < 8; i++) {
            int r = rb + (i << 4);
            float4 va = *(const float4*)(A + (size_t)(m0 + r) * HID + k0 + c4);
            store_split64(Ah, Al, r, c4, va);
            float4 vw = *(const float4*)(W + (size_t)(n0 + r) * HID + k0 + c4);
            store_split64(Bh, Bl, r, c4, vw);
        }
        __syncthreads();
#pragma unroll
        for (int ks = 0; ks < 4; ks++) {
            uint32_t ah0,ah1,ah2,ah3, al0,al1,al2,al3;
            ldsm4(laddr(uAh, 16*wid, 2*ks, lane, 7), ah0,ah1,ah2,ah3);
            ldsm4(laddr(uAl, 16*wid, 2*ks, lane, 7), al0,al1,al2,al3);
#pragma unroll
            for (int p = 0; p < 8; p++) {
                uint32_t bh0,bh1,bh2,bh3, bl0,bl1,bl2,bl3;
                ldsm4(laddr(uBh, 16*p, 2*ks, lane, 7), bh0,bh1,bh2,bh3);
                ldsm4(laddr(uBl, 16*p, 2*ks, lane, 7), bl0,bl1,bl2,bl3);
                mma16816(acc[2*p],   ah0,ah1,ah2,ah3, bh0,bh2);
                mma16816(acc[2*p],   ah0,ah1,ah2,ah3, bl0,bl2);
                mma16816(acc[2*p],   al0,al1,al2,al3, bh0,bh2);
                mma16816(acc[2*p+1], ah0,ah1,ah2,ah3, bh1,bh3);
                mma16816(acc[2*p+1], ah0,ah1,ah2,ah3, bl1,bl3);
                mma16816(acc[2*p+1], al0,al1,al2,al3, bh1,bh3);
            }
        }
        __syncthreads();
    }

    int r0 = m0 + 16*wid + (lane >> 2);
    int cb = 2*(lane & 3);
    if (dest_sel < 3) {
#pragma unroll
        for (int t = 0; t < 16; t++) {
            int col = n0 + 8*t + cb;
            int h = col >> 6, d = col & 63;
#pragma unroll
            for (int rr = 0; rr < 2; rr++) {
                int row = r0 + rr*8;
                int b = row >> 11, s = row & (SEQ-1);
                float2 v = rr ? make_float2(acc[t][2], acc[t][3])
                              : make_float2(acc[t][0], acc[t][1]);
                *(float2*)(&dst[(((size_t)(b<<4) + h) * SEQ + s) * HDIM + d]) = v;
            }
        }
    } else {
#pragma unroll
        for (int t = 0; t < 16; t++) {
            int col = n0 + 8*t + cb;
            *(float2*)(&dst[(size_t)r0 * HID + col])     = make_float2(acc[t][0], acc[t][1]);
            *(float2*)(&dst[(size_t)(r0+8) * HID + col]) = make_float2(acc[t][2], acc[t][3]);
        }
    }
}

// ---------------- split-bf16 tensor flash attention ------------------------
// BQ=128, BK=128. 8 warps; warp w owns q-rows 16w..16w+15 (full row stats in-warp).
#define FLASH_SMEM_BYTES (6*8192*2)   // Qh,Ql,Kh,Kl (128x64) + Vh,Vl (64x128) = 96KB

__global__ void __launch_bounds__(256, 1) flash_mma_kernel() {
    extern __shared__ __nv_bfloat16 smf[];
    __nv_bfloat16 *Qh = smf,          *Ql = smf + 8192;
    __nv_bfloat16 *Kh = smf + 16384,  *Kl = smf + 24576;
    __nv_bfloat16 *Vh = smf + 32768,  *Vl = smf + 40960;
    int tid = threadIdx.x, lane = tid & 31, wid = tid >> 5;
    int bh = blockIdx.y;
    int q0 = blockIdx.x << 7;
    const float* Qp = g_q + (size_t)bh * SEQ * HDIM;
    const float* Kp = g_k + (size_t)bh * SEQ * HDIM;
    const float* Vp = g_v + (size_t)bh * SEQ * HDIM;

    uint32_t uQh = (uint32_t)__cvta_generic_to_shared(Qh);
    uint32_t uQl = (uint32_t)__cvta_generic_to_shared(Ql);
    uint32_t uKh = (uint32_t)__cvta_generic_to_shared(Kh);
    uint32_t uKl = (uint32_t)__cvta_generic_to_shared(Kl);
    uint32_t uVh = (uint32_t)__cvta_generic_to_shared(Vh);
    uint32_t uVl = (uint32_t)__cvta_generic_to_shared(Vl);

    int rb = tid >> 4, c4 = (tid & 15) << 2;

    // Q tile (scaled by 1/sqrt(64)=0.125 before split)
#pragma unroll
    for (int i = 0; i < 8; i++) {
        int r = rb + (i << 4);
        float4 v = *(const float4*)(Qp + (size_t)(q0 + r) * HDIM + c4);
        v.x *= 0.125f; v.y *= 0.125f; v.z *= 0.125f; v.w *= 0.125f;
        store_split64(Qh, Ql, r, c4, v);
    }

    float o[8][4];
#pragma unroll
    for (int t = 0; t < 8; t++)
#pragma unroll
        for (int j = 0; j < 4; j++) o[t][j] = 0.f;
    float m0r = -INFINITY, m1r = -INFINITY, l0r = 0.f, l1r = 0.f;

    for (int kv = 0; kv < SEQ; kv += 128) {
        __syncthreads();   // previous compute done (also publishes Q on iter 0)
#pragma unroll
        for (int i = 0; i < 8; i++) {
            int r = rb + (i << 4);
            float4 kvv = *(const float4*)(Kp + (size_t)(kv + r) * HDIM + c4);
            store_split64(Kh, Kl, r, c4, kvv);
            float4 vv = *(const float4*)(Vp + (size_t)(kv + r) * HDIM + c4);
            // transpose V into Vt[d][k] (64 rows x 128 cols), swizzled
            float vals[4] = {vv.x, vv.y, vv.z, vv.w};
#pragma unroll
            for (int j = 0; j < 4; j++) {
                int d = c4 + j;
                int eo = d*128 + ((((r>>3) ^ (d&7)))<<3) + (r&7);
                float val = vals[j];
                float hh = bfhi(val);
                Vh[eo] = __float2bfloat16(val);
                Vl[eo] = __float2bfloat16(val - hh);
            }
        }
        __syncthreads();

        // ---- S = Q K^T (split-bf16, 3 mma) ----
        float s[16][4];
#pragma unroll
        for (int t = 0; t < 16; t++)
#pragma unroll
            for (int j = 0; j < 4; j++) s[t][j] = 0.f;
#pragma unroll
        for (int ks = 0; ks < 4; ks++) {
            uint32_t ah0,ah1,ah2,ah3, al0,al1,al2,al3;
            ldsm4(laddr(uQh, 16*wid, 2*ks, lane, 7), ah0,ah1,ah2,ah3);
            ldsm4(laddr(uQl, 16*wid, 2*ks, lane, 7), al0,al1,al2,al3);
#pragma unroll
            for (int p = 0; p < 8; p++) {
                uint32_t bh0,bh1,bh2,bh3, bl0,bl1,bl2,bl3;
                ldsm4(laddr(uKh, 16*p, 2*ks, lane, 7), bh0,bh1,bh2,bh3);
                ldsm4(laddr(uKl, 16*p, 2*ks, lane, 7), bl0,bl1,bl2,bl3);
                mma16816(s[2*p],   ah0,ah1,ah2,ah3, bh0,bh2);
                mma16816(s[2*p],   ah0,ah1,ah2,ah3, bl0,bl2);
                mma16816(s[2*p],   al0,al1,al2,al3, bh0,bh2);
                mma16816(s[2*p+1], ah0,ah1,ah2,ah3, bh1,bh3);
                mma16816(s[2*p+1], ah0,ah1,ah2,ah3, bl1,bl3);
                mma16816(s[2*p+1], al0,al1,al2,al3, bh1,bh3);
            }
        }

        // ---- online softmax (rows live within a quad) ----
        float mx0 = -INFINITY, mx1 = -INFINITY;
#pragma unroll
        for (int t = 0; t < 16; t++) {
            mx0 = fmaxf(mx0, fmaxf(s[t][0], s[t][1]));
            mx1 = fmaxf(mx1, fmaxf(s[t][2], s[t][3]));
        }
        mx0 = fmaxf(mx0, __shfl_xor_sync(0xffffffffu, mx0, 1));
        mx0 = fmaxf(mx0, __shfl_xor_sync(0xffffffffu, mx0, 2));
        mx1 = fmaxf(mx1, __shfl_xor_sync(0xffffffffu, mx1, 1));
        mx1 = fmaxf(mx1, __shfl_xor_sync(0xffffffffu, mx1, 2));
        float nm0 = fmaxf(m0r, mx0), nm1 = fmaxf(m1r, mx1);
        float c0 = __expf(m0r - nm0), c1 = __expf(m1r - nm1);
        m0r = nm0; m1r = nm1;
        float sum0 = 0.f, sum1 = 0.f;
#pragma unroll
        for (int t = 0; t < 16; t++) {
            s[t][0] = __expf(s[t][0] - nm0); sum0 += s[t][0];
            s[t][1] = __expf(s[t][1] - nm0); sum0 += s[t][1];
            s[t][2] = __expf(s[t][2] - nm1); sum1 += s[t][2];
            s[t][3] = __expf(s[t][3] - nm1); sum1 += s[t][3];
        }
        sum0 += __shfl_xor_sync(0xffffffffu, sum0, 1);
        sum0 += __shfl_xor_sync(0xffffffffu, sum0, 2);
        sum1 += __shfl_xor_sync(0xffffffffu, sum1, 1);
        sum1 += __shfl_xor_sync(0xffffffffu, sum1, 2);
        l0r = l0r * c0 + sum0;
        l1r = l1r * c1 + sum1;
#pragma unroll
        for (int t = 0; t < 8; t++) {
            o[t][0] *= c0; o[t][1] *= c0; o[t][2] *= c1; o[t][3] *= c1;
        }

        // ---- O += P V (P from S fragments, split-bf16) ----
#pragma unroll
        for (int km = 0; km < 8; km++) {
            int t0 = 2*km, t1 = t0 + 1;
            uint32_t a0h = pack2(s[t0][0], s[t0][1]);
            uint32_t a1h = pack2(s[t0][2], s[t0][3]);
            uint32_t a2h = pack2(s[t1][0], s[t1][1]);
            uint32_t a3h = pack2(s[t1][2], s[t1][3]);
            uint32_t a0l = pack2(s[t0][0]-bfhi(s[t0][0]), s[t0][1]-bfhi(s[t0][1]));
            uint32_t a1l = pack2(s[t0][2]-bfhi(s[t0][2]), s[t0][3]-bfhi(s[t0][3]));
            uint32_t a2l = pack2(s[t1][0]-bfhi(s[t1][0]), s[t1][1]-bfhi(s[t1][1]));
            uint32_t a3l = pack2(s[t1][2]-bfhi(s[t1][2]), s[t1][3]-bfhi(s[t1][3]));
#pragma unroll
            for (int p = 0; p < 4; p++) {
                uint32_t bh0,bh1,bh2,bh3, bl0,bl1,bl2,bl3;
                ldsm4(laddr(uVh, 16*p, 2*km, lane, 8), bh0,bh1,bh2,bh3);
                ldsm4(laddr(uVl, 16*p, 2*km, lane, 8), bl0,bl1,bl2,bl3);
                mma16816(o[2*p],   a0h,a1h,a2h,a3h, bh0,bh2);
                mma16816(o[2*p],   a0h,a1h,a2h,a3h, bl0,bl2);
                mma16816(o[2*p],   a0l,a1l,a2l,a3l, bh0,bh2);
                mma16816(o[2*p+1], a0h,a1h,a2h,a3h, bh1,bh3);
                mma16816(o[2*p+1], a0h,a1h,a2h,a3h, bl1,bl3);
                mma16816(o[2*p+1], a0l,a1l,a2l,a3l, bh1,bh3);
            }
        }
    }

    // ---- epilogue ----
    int b = bh >> 4, h = bh & 15;
    int r0 = q0 + 16*wid + (lane >> 2);
    float inv0 = 1.0f / l0r, inv1 = 1.0f / l1r;
#pragma unroll
    for (int t = 0; t < 8; t++) {
        int d = 8*t + 2*(lane & 3);
        *(float2*)(&g_attn[((size_t)b * SEQ + r0) * HID + (h<<6) + d]) =
            make_float2(o[t][0]*inv0, o[t][1]*inv0);
        *(float2*)(&g_attn[((size_t)b * SEQ + r0 + 8) * HID + (h<<6) + d]) =
            make_float2(o[t][2]*inv1, o[t][3]*inv1);
    }
}

// ---------------- launch ----------------------------------------------------
extern "C" void kernel_launch(void* const* d_in, const int* in_sizes, int n_in,
                              void* d_out, int out_size) {
    const float* x  = (const float*)d_in[0];
    const float* wq = (const float*)d_in[1];
    const float* wk = (const float*)d_in[2];
    const float* wv = (const float*)d_in[3];
    const float* wo = (const float*)d_in[4];
    float* out = (float*)d_out;

    cudaFuncSetAttribute(gemm_mma_kernel,
                         cudaFuncAttributeMaxDynamicSharedMemorySize, GEMM_SMEM_BYTES);
    cudaFuncSetAttribute(flash_mma_kernel,
                         cudaFuncAttributeMaxDynamicSharedMemorySize, FLASH_SMEM_BYTES);

    rope_table_kernel<<<(SEQ*32 + 255)/256, 256>>>();

    dim3 gg(HID/128, NTOK/128);                 // (8, 32)
    gemm_mma_kernel<<<gg, 256, GEMM_SMEM_BYTES>>>(x, wq, nullptr, 0);
    gemm_mma_kernel<<<gg, 256, GEMM_SMEM_BYTES>>>(x, wk, nullptr, 1);
    gemm_mma_kernel<<<gg, 256, GEMM_SMEM_BYTES>>>(x, wv, nullptr, 2);

    int npairs = BATCH*NHEADS*SEQ*32;
    rope_apply_kernel<<<npairs/256, 256>>>(0);
    rope_apply_kernel<<<npairs/256, 256>>>(1);

    dim3 fg(SEQ/128, BATCH*NHEADS);             // (16, 32)
    flash_mma_kernel<<<fg, 256, FLASH_SMEM_BYTES>>>();

    gemm_mma_kernel<<<gg, 256, GEMM_SMEM_BYTES>>>(nullptr, wo, out, 3);
}

// round 6
// speedup vs baseline: 2.8516x; 1.4571x over previous
#include <cuda_runtime.h>
#include <cuda_bf16.h>
#include <math.h>
#include <stdint.h>

#define NHEADS 16
#define HDIM   64
#define SEQ    2048
#define BATCH  2
#define HID    1024
#define NTOK   (BATCH*SEQ)      // 4096

typedef __nv_bfloat16 bf16;
typedef __nv_bfloat162 bf162;

// ---------------- bf16 hi/lo plane scratch (device globals) ----------------
__device__ bf16 g_xh[(size_t)NTOK*HID],  g_xl[(size_t)NTOK*HID];
__device__ bf16 g_wwh[(size_t)4*HID*HID], g_wwl[(size_t)4*HID*HID]; // wq,wk,wv,wo
__device__ bf16 g_qh[(size_t)NTOK*HID],  g_ql[(size_t)NTOK*HID];   // [b*16+h][s][d]
__device__ bf16 g_kh[(size_t)NTOK*HID],  g_kl[(size_t)NTOK*HID];
__device__ bf16 g_vh[(size_t)NTOK*HID],  g_vl[(size_t)NTOK*HID];
__device__ bf16 g_ah[(size_t)NTOK*HID],  g_al[(size_t)NTOK*HID];   // attn out [t][h*64+d]
__device__ float g_cos[SEQ*32];
__device__ float g_sin[SEQ*32];

// ---------------- helpers ---------------------------------------------------
__device__ __forceinline__ uint32_t pack2(float lo, float hi) {
    bf162 h = __floats2bfloat162_rn(lo, hi);
    return *reinterpret_cast<uint32_t*>(&h);
}
__device__ __forceinline__ float bfhi(float x) {
    return __bfloat162float(__float2bfloat16(x));
}
__device__ __forceinline__ void ldsm4(uint32_t addr, uint32_t &r0, uint32_t &r1,
                                      uint32_t &r2, uint32_t &r3) {
    asm volatile("ldmatrix.sync.aligned.m8n8.x4.shared.b16 {%0,%1,%2,%3}, [%4];\n"
                 : "=r"(r0), "=r"(r1), "=r"(r2), "=r"(r3) : "r"(addr));
}
__device__ __forceinline__ void ldsm4t(uint32_t addr, uint32_t &r0, uint32_t &r1,
                                       uint32_t &r2, uint32_t &r3) {
    asm volatile("ldmatrix.sync.aligned.m8n8.x4.trans.shared.b16 {%0,%1,%2,%3}, [%4];\n"
                 : "=r"(r0), "=r"(r1), "=r"(r2), "=r"(r3) : "r"(addr));
}
__device__ __forceinline__ void mma16816(float d[4], uint32_t a0, uint32_t a1,
                                         uint32_t a2, uint32_t a3,
                                         uint32_t b0, uint32_t b1) {
    asm volatile("mma.sync.aligned.m16n8k16.row.col.f32.bf16.bf16.f32 "
                 "{%0,%1,%2,%3},{%4,%5,%6,%7},{%8,%9},{%0,%1,%2,%3};\n"
                 : "+f"(d[0]), "+f"(d[1]), "+f"(d[2]), "+f"(d[3])
                 : "r"(a0), "r"(a1), "r"(a2), "r"(a3), "r"(b0), "r"(b1));
}
// smem tile layout: rows of 64 bf16 = 128B, 8 chunks of 16B, chunk ^= (row&7)
__device__ __forceinline__ uint32_t laddr(uint32_t base, int row0, int chunk0,
                                          int lane) {
    int r = row0 + (lane & 15);
    int c = chunk0 + (lane >> 4);
    return base + (r << 7) + ((c ^ (r & 7)) << 4);
}
__device__ __forceinline__ void cpa16(uint32_t dst, const void* src) {
    asm volatile("cp.async.cg.shared.global [%0], [%1], 16;" :: "r"(dst), "l"(src) : "memory");
}
#define CPA_COMMIT()  asm volatile("cp.async.commit_group;" ::: "memory")
#define CPA_WAIT(n)   asm volatile("cp.async.wait_group %0;" :: "n"(n) : "memory")

// ---------------- RoPE table (double sincos, fast-math-proof) ---------------
__global__ void rope_table_kernel() {
    int idx = blockIdx.x * blockDim.x + threadIdx.x;
    if (idx >= SEQ*32) return;
    int s = idx >> 5, i = idx & 31;
    double invd = pow(10000.0, -((double)i) / 32.0);
    float ang = (float)s * (float)invd;
    double sv, cv;
    sincos((double)ang, &sv, &cv);
    g_cos[idx] = (float)cv;
    g_sin[idx] = (float)sv;
}

// ---------------- convert x + 4 weights to hi/lo planes ---------------------
__global__ void __launch_bounds__(256) convert_kernel(
    const float* __restrict__ x,  const float* __restrict__ wq,
    const float* __restrict__ wk, const float* __restrict__ wv,
    const float* __restrict__ wo)
{
    int idx = blockIdx.x * 256 + threadIdx.x;         // float4 index, 2M total
    const float* src; bf16 *dh, *dl; size_t off;
    if (idx < 1048576) {
        src = x + (size_t)idx*4; dh = g_xh; dl = g_xl; off = (size_t)idx*4;
    } else {
        int j = idx - 1048576;
        int w = j >> 18;                               // 256K float4 per weight
        int r = j & 262143;
        src = (w==0?wq : w==1?wk : w==2?wv : wo) + (size_t)r*4;
        dh = g_wwh; dl = g_wwl; off = (size_t)j*4;
    }
    float4 v = *(const float4*)src;
    float h0=bfhi(v.x), h1=bfhi(v.y), h2=bfhi(v.z), h3=bfhi(v.w);
    *(bf162*)(dh+off)   = __floats2bfloat162_rn(v.x, v.y);
    *(bf162*)(dh+off+2) = __floats2bfloat162_rn(v.z, v.w);
    *(bf162*)(dl+off)   = __floats2bfloat162_rn(v.x-h0, v.y-h1);
    *(bf162*)(dl+off+2) = __floats2bfloat162_rn(v.z-h2, v.w-h3);
}

// ============ plane GEMM: C[M,N] = A[M,K] * W[N,K]^T (split-3 bf16) =========
// 128x128 tile, BK=64, 256 threads, double-buffered cp.async.
// asel: 0 = x planes, 1 = attn planes. wsel: 0..3 weight. dest_sel:
//   0/1 -> q/k planes with fused RoPE (q scaled 0.125); 2 -> v planes; 3 -> fp32 out.
#define GEMM_SMEM (2*65536)

__global__ void __launch_bounds__(256, 1) gemm_pl_kernel(
    float* __restrict__ outp, int asel, int wsel, int dest_sel)
{
    extern __shared__ char sm[];
    uint32_t sbase = (uint32_t)__cvta_generic_to_shared(sm);
    const bf16* Ahp = asel ? g_ah : g_xh;
    const bf16* Alp = asel ? g_al : g_xl;
    const bf16* Whp = g_wwh + (size_t)wsel * HID * HID;
    const bf16* Wlp = g_wwl + (size_t)wsel * HID * HID;

    int tid = threadIdx.x, lane = tid & 31, wid = tid >> 5;
    int m0 = blockIdx.y << 7, n0 = blockIdx.x << 7;

    // ---- cp.async issue of one K-slab into buffer b ----
    auto issue = [&](int s, int b) {
        int k0 = s << 6;
        uint32_t bufb = sbase + b * 65536;
#pragma unroll
        for (int i = 0; i < 16; i++) {
            int g = (i << 8) + tid;
            int plane = g >> 10;                 // 0 Ah,1 Al,2 Wh,3 Wl
            int rem = g & 1023, row = rem >> 3, ch = rem & 7;
            const bf16* sp = (plane==0) ? Ahp : (plane==1) ? Alp
                           : (plane==2) ? Whp : Wlp;
            int grow = (plane < 2 ? m0 : n0) + row;
            const void* src = sp + (size_t)grow * HID + k0 + ch * 8;
            uint32_t dst = bufb + plane*16384 + (row<<7) + ((ch ^ (row&7)) << 4);
            cpa16(dst, src);
        }
        CPA_COMMIT();
    };

    float acc[16][4];
#pragma unroll
    for (int t = 0; t < 16; t++)
#pragma unroll
        for (int j = 0; j < 4; j++) acc[t][j] = 0.f;

    issue(0, 0);
    for (int s = 0; s < 16; s++) {
        int bufi = s & 1;
        if (s + 1 < 16) { issue(s + 1, bufi ^ 1); CPA_WAIT(1); }
        else            { CPA_WAIT(0); }
        __syncthreads();
        uint32_t b0 = sbase + bufi * 65536;
        uint32_t uAh = b0, uAl = b0 + 16384, uWh = b0 + 32768, uWl = b0 + 49152;
#pragma unroll
        for (int ks = 0; ks < 4; ks++) {
            uint32_t ah0,ah1,ah2,ah3, al0,al1,al2,al3;
            ldsm4(laddr(uAh, 16*wid, 2*ks, lane), ah0,ah1,ah2,ah3);
            ldsm4(laddr(uAl, 16*wid, 2*ks, lane), al0,al1,al2,al3);
#pragma unroll
            for (int p = 0; p < 8; p++) {
                uint32_t bh0,bh1,bh2,bh3, bl0,bl1,bl2,bl3;
                ldsm4(laddr(uWh, 16*p, 2*ks, lane), bh0,bh1,bh2,bh3);
                ldsm4(laddr(uWl, 16*p, 2*ks, lane), bl0,bl1,bl2,bl3);
                mma16816(acc[2*p],   ah0,ah1,ah2,ah3, bh0,bh2);
                mma16816(acc[2*p],   ah0,ah1,ah2,ah3, bl0,bl2);
                mma16816(acc[2*p],   al0,al1,al2,al3, bh0,bh2);
                mma16816(acc[2*p+1], ah0,ah1,ah2,ah3, bh1,bh3);
                mma16816(acc[2*p+1], ah0,ah1,ah2,ah3, bl1,bl3);
                mma16816(acc[2*p+1], al0,al1,al2,al3, bh1,bh3);
            }
        }
        __syncthreads();
    }

    // ---- epilogue ----
    int r0 = m0 + 16*wid + (lane >> 2);
    int cb = 2*(lane & 3);
    if (dest_sel == 3) {
#pragma unroll
        for (int t = 0; t < 16; t++) {
            int col = n0 + 8*t + cb;
            *(float2*)(&outp[(size_t)r0 * HID + col])     = make_float2(acc[t][0], acc[t][1]);
            *(float2*)(&outp[(size_t)(r0+8) * HID + col]) = make_float2(acc[t][2], acc[t][3]);
        }
    } else {
        bf16 *dh, *dl;
        if      (dest_sel == 0) { dh = g_qh; dl = g_ql; }
        else if (dest_sel == 1) { dh = g_kh; dl = g_kl; }
        else                    { dh = g_vh; dl = g_vl; }
        float qs = (dest_sel == 0) ? 0.125f : 1.0f;
#pragma unroll
        for (int t = 0; t < 16; t++) {
            int col = n0 + 8*t + cb;                 // even
            int h = col >> 6, d = col & 63, d2 = d >> 1;
#pragma unroll
            for (int rr = 0; rr < 2; rr++) {
                int row = r0 + rr*8;
                int b = row >> 11, sq = row & (SEQ-1);
                float v0 = acc[t][rr*2], v1 = acc[t][rr*2+1];
                if (dest_sel < 2) {                  // RoPE
                    float c  = g_cos[(sq<<5) + d2];
                    float sn = g_sin[(sq<<5) + d2];
                    float o0 = v0*c - v1*sn;
                    float o1 = v0*sn + v1*c;
                    v0 = o0 * qs; v1 = o1 * qs;
                }
                size_t off = (((size_t)(b<<4) + h) * SEQ + sq) * HDIM + d;
                float h0 = bfhi(v0), h1 = bfhi(v1);
                *(bf162*)(dh + off) = __floats2bfloat162_rn(v0, v1);
                *(bf162*)(dl + off) = __floats2bfloat162_rn(v0-h0, v1-h1);
            }
        }
    }
}

// ============ plane flash attention (split-3 bf16 mma.sync) =================
// BQ=BK=128; 8 warps, warp w owns q-rows 16w..16w+15. Double-buffered K/V.
// smem: Qh(16K) Ql(16K) | 2 x [Kh Kl Vh Vl](64K) = 160KB
#define FLASH_SMEM (32768 + 2*65536)

__global__ void __launch_bounds__(256, 1) flash_pl_kernel() {
    extern __shared__ char smc[];
    uint32_t sbase = (uint32_t)__cvta_generic_to_shared(smc);
    int tid = threadIdx.x, lane = tid & 31, wid = tid >> 5;
    int bh = blockIdx.y;
    int q0 = blockIdx.x << 7;
    size_t hb = (size_t)bh * SEQ * HDIM;

    uint32_t uQh = sbase, uQl = sbase + 16384;

    // Q planes (group with tile 0)
    {
#pragma unroll
        for (int i = 0; i < 8; i++) {
            int g = (i << 8) + tid;
            int plane = g >> 10, rem = g & 1023, row = rem >> 3, ch = rem & 7;
            const bf16* sp = plane ? g_ql : g_qh;
            const void* src = sp + hb + (size_t)(q0 + row) * HDIM + ch * 8;
            uint32_t dst = sbase + plane*16384 + (row<<7) + ((ch ^ (row&7)) << 4);
            cpa16(dst, src);
        }
    }
    auto issue_kv = [&](int t, int b) {
        int kv = t << 7;
        uint32_t bufb = sbase + 32768 + b * 65536;
#pragma unroll
        for (int i = 0; i < 16; i++) {
            int g = (i << 8) + tid;
            int plane = g >> 10;                 // 0 Kh,1 Kl,2 Vh,3 Vl
            int rem = g & 1023, row = rem >> 3, ch = rem & 7;
            const bf16* sp = (plane==0) ? g_kh : (plane==1) ? g_kl
                           : (plane==2) ? g_vh : g_vl;
            const void* src = sp + hb + (size_t)(kv + row) * HDIM + ch * 8;
            uint32_t dst = bufb + plane*16384 + (row<<7) + ((ch ^ (row&7)) << 4);
            cpa16(dst, src);
        }
        CPA_COMMIT();
    };

    float o[8][4];
#pragma unroll
    for (int t = 0; t < 8; t++)
#pragma unroll
        for (int j = 0; j < 4; j++) o[t][j] = 0.f;
    float m0r = -INFINITY, m1r = -INFINITY, l0r = 0.f, l1r = 0.f;

    issue_kv(0, 0);   // commits Q + KV0 together
    for (int t = 0; t < 16; t++) {
        int bufi = t & 1;
        if (t + 1 < 16) { issue_kv(t + 1, bufi ^ 1); CPA_WAIT(1); }
        else            { CPA_WAIT(0); }
        __syncthreads();
        uint32_t b0 = sbase + 32768 + bufi * 65536;
        uint32_t uKh = b0, uKl = b0 + 16384, uVh = b0 + 32768, uVl = b0 + 49152;

        // ---- S = Q K^T ----
        float s[16][4];
#pragma unroll
        for (int tt = 0; tt < 16; tt++)
#pragma unroll
            for (int j = 0; j < 4; j++) s[tt][j] = 0.f;
#pragma unroll
        for (int ks = 0; ks < 4; ks++) {
            uint32_t ah0,ah1,ah2,ah3, al0,al1,al2,al3;
            ldsm4(laddr(uQh, 16*wid, 2*ks, lane), ah0,ah1,ah2,ah3);
            ldsm4(laddr(uQl, 16*wid, 2*ks, lane), al0,al1,al2,al3);
#pragma unroll
            for (int p = 0; p < 8; p++) {
                uint32_t bh0,bh1,bh2,bh3, bl0,bl1,bl2,bl3;
                ldsm4(laddr(uKh, 16*p, 2*ks, lane), bh0,bh1,bh2,bh3);
                ldsm4(laddr(uKl, 16*p, 2*ks, lane), bl0,bl1,bl2,bl3);
                mma16816(s[2*p],   ah0,ah1,ah2,ah3, bh0,bh2);
                mma16816(s[2*p],   ah0,ah1,ah2,ah3, bl0,bl2);
                mma16816(s[2*p],   al0,al1,al2,al3, bh0,bh2);
                mma16816(s[2*p+1], ah0,ah1,ah2,ah3, bh1,bh3);
                mma16816(s[2*p+1], ah0,ah1,ah2,ah3, bl1,bl3);
                mma16816(s[2*p+1], al0,al1,al2,al3, bh1,bh3);
            }
        }

        // ---- online softmax (row pairs live in quads) ----
        float mx0 = -INFINITY, mx1 = -INFINITY;
#pragma unroll
        for (int tt = 0; tt < 16; tt++) {
            mx0 = fmaxf(mx0, fmaxf(s[tt][0], s[tt][1]));
            mx1 = fmaxf(mx1, fmaxf(s[tt][2], s[tt][3]));
        }
        mx0 = fmaxf(mx0, __shfl_xor_sync(0xffffffffu, mx0, 1));
        mx0 = fmaxf(mx0, __shfl_xor_sync(0xffffffffu, mx0, 2));
        mx1 = fmaxf(mx1, __shfl_xor_sync(0xffffffffu, mx1, 1));
        mx1 = fmaxf(mx1, __shfl_xor_sync(0xffffffffu, mx1, 2));
        float nm0 = fmaxf(m0r, mx0), nm1 = fmaxf(m1r, mx1);
        float c0 = __expf(m0r - nm0), c1 = __expf(m1r - nm1);
        m0r = nm0; m1r = nm1;
        float sum0 = 0.f, sum1 = 0.f;
#pragma unroll
        for (int tt = 0; tt < 16; tt++) {
            s[tt][0] = __expf(s[tt][0] - nm0); sum0 += s[tt][0];
            s[tt][1] = __expf(s[tt][1] - nm0); sum0 += s[tt][1];
            s[tt][2] = __expf(s[tt][2] - nm1); sum1 += s[tt][2];
            s[tt][3] = __expf(s[tt][3] - nm1); sum1 += s[tt][3];
        }
        sum0 += __shfl_xor_sync(0xffffffffu, sum0, 1);
        sum0 += __shfl_xor_sync(0xffffffffu, sum0, 2);
        sum1 += __shfl_xor_sync(0xffffffffu, sum1, 1);
        sum1 += __shfl_xor_sync(0xffffffffu, sum1, 2);
        l0r = l0r * c0 + sum0;
        l1r = l1r * c1 + sum1;
#pragma unroll
        for (int tt = 0; tt < 8; tt++) {
            o[tt][0] *= c0; o[tt][1] *= c0; o[tt][2] *= c1; o[tt][3] *= c1;
        }

        // ---- O += P V (V via trans-ldmatrix on row-major planes) ----
#pragma unroll
        for (int km = 0; km < 8; km++) {
            int t0 = 2*km, t1 = t0 + 1;
            uint32_t a0h = pack2(s[t0][0], s[t0][1]);
            uint32_t a1h = pack2(s[t0][2], s[t0][3]);
            uint32_t a2h = pack2(s[t1][0], s[t1][1]);
            uint32_t a3h = pack2(s[t1][2], s[t1][3]);
            uint32_t a0l = pack2(s[t0][0]-bfhi(s[t0][0]), s[t0][1]-bfhi(s[t0][1]));
            uint32_t a1l = pack2(s[t0][2]-bfhi(s[t0][2]), s[t0][3]-bfhi(s[t0][3]));
            uint32_t a2l = pack2(s[t1][0]-bfhi(s[t1][0]), s[t1][1]-bfhi(s[t1][1]));
            uint32_t a3l = pack2(s[t1][2]-bfhi(s[t1][2]), s[t1][3]-bfhi(s[t1][3]));
#pragma unroll
            for (int p = 0; p < 4; p++) {
                uint32_t vh0,vh1,vh2,vh3, vl0,vl1,vl2,vl3;
                ldsm4t(laddr(uVh, 16*km, 2*p, lane), vh0,vh1,vh2,vh3);
                ldsm4t(laddr(uVl, 16*km, 2*p, lane), vl0,vl1,vl2,vl3);
                mma16816(o[2*p],   a0h,a1h,a2h,a3h, vh0,vh1);
                mma16816(o[2*p],   a0h,a1h,a2h,a3h, vl0,vl1);
                mma16816(o[2*p],   a0l,a1l,a2l,a3l, vh0,vh1);
                mma16816(o[2*p+1], a0h,a1h,a2h,a3h, vh2,vh3);
                mma16816(o[2*p+1], a0h,a1h,a2h,a3h, vl2,vl3);
                mma16816(o[2*p+1], a0l,a1l,a2l,a3l, vh2,vh3);
            }
        }
        __syncthreads();
    }

    // ---- epilogue: normalize, split to attn planes ----
    int b = bh >> 4, h = bh & 15;
    int r0 = q0 + 16*wid + (lane >> 2);
    float inv0 = 1.0f / l0r, inv1 = 1.0f / l1r;
#pragma unroll
    for (int t = 0; t < 8; t++) {
        int d = 8*t + 2*(lane & 3);
        size_t off0 = ((size_t)b * SEQ + r0)     * HID + (h<<6) + d;
        size_t off1 = ((size_t)b * SEQ + r0 + 8) * HID + (h<<6) + d;
        float v0 = o[t][0]*inv0, v1 = o[t][1]*inv0;
        float v2 = o[t][2]*inv1, v3 = o[t][3]*inv1;
        float h0=bfhi(v0), h1=bfhi(v1), h2=bfhi(v2), h3=bfhi(v3);
        *(bf162*)(g_ah + off0) = __floats2bfloat162_rn(v0, v1);
        *(bf162*)(g_al + off0) = __floats2bfloat162_rn(v0-h0, v1-h1);
        *(bf162*)(g_ah + off1) = __floats2bfloat162_rn(v2, v3);
        *(bf162*)(g_al + off1) = __floats2bfloat162_rn(v2-h2, v3-h3);
    }
}

// ---------------- launch ----------------------------------------------------
extern "C" void kernel_launch(void* const* d_in, const int* in_sizes, int n_in,
                              void* d_out, int out_size) {
    const float* x  = (const float*)d_in[0];
    const float* wq = (const float*)d_in[1];
    const float* wk = (const float*)d_in[2];
    const float* wv = (const float*)d_in[3];
    const float* wo = (const float*)d_in[4];
    float* out = (float*)d_out;

    cudaFuncSetAttribute(gemm_pl_kernel,
                         cudaFuncAttributeMaxDynamicSharedMemorySize, GEMM_SMEM);
    cudaFuncSetAttribute(flash_pl_kernel,
                         cudaFuncAttributeMaxDynamicSharedMemorySize, FLASH_SMEM);

    rope_table_kernel<<<(SEQ*32 + 255)/256, 256>>>();
    convert_kernel<<<8192, 256>>>(x, wq, wk, wv, wo);

    dim3 gg(HID/128, NTOK/128);                 // (8, 32)
    gemm_pl_kernel<<<gg, 256, GEMM_SMEM>>>(nullptr, 0, 0, 0);  // q (+rope, scaled)
    gemm_pl_kernel<<<gg, 256, GEMM_SMEM>>>(nullptr, 0, 1, 1);  // k (+rope)
    gemm_pl_kernel<<<gg, 256, GEMM_SMEM>>>(nullptr, 0, 2, 2);  // v

    dim3 fg(SEQ/128, BATCH*NHEADS);             // (16, 32)
    flash_pl_kernel<<<fg, 256, FLASH_SMEM>>>();

    gemm_pl_kernel<<<gg, 256, GEMM_SMEM>>>(out, 1, 3, 3);      // attn * wo
}

// round 7
// speedup vs baseline: 2.8969x; 1.0159x over previous
#include <cuda_runtime.h>
#include <cuda_bf16.h>
#include <math.h>
#include <stdint.h>

#define NHEADS 16
#define HDIM   64
#define SEQ    2048
#define BATCH  2
#define HID    1024
#define NTOK   (BATCH*SEQ)      // 4096

typedef __nv_bfloat16 bf16;
typedef __nv_bfloat162 bf162;

// ---------------- bf16 hi/lo plane scratch (device globals) ----------------
__device__ bf16 g_xh[(size_t)NTOK*HID],  g_xl[(size_t)NTOK*HID];
__device__ bf16 g_wwh[(size_t)4*HID*HID], g_wwl[(size_t)4*HID*HID]; // wq,wk,wv,wo
__device__ bf16 g_qh[(size_t)NTOK*HID],  g_ql[(size_t)NTOK*HID];   // [b*16+h][s][d]
__device__ bf16 g_kh[(size_t)NTOK*HID],  g_kl[(size_t)NTOK*HID];
__device__ bf16 g_vh[(size_t)NTOK*HID],  g_vl[(size_t)NTOK*HID];
__device__ bf16 g_ah[(size_t)NTOK*HID],  g_al[(size_t)NTOK*HID];   // attn out [t][h*64+d]
__device__ float g_cos[SEQ*32];
__device__ float g_sin[SEQ*32];

// ---------------- helpers ---------------------------------------------------
__device__ __forceinline__ uint32_t pack2(float lo, float hi) {
    bf162 h = __floats2bfloat162_rn(lo, hi);
    return *reinterpret_cast<uint32_t*>(&h);
}
__device__ __forceinline__ float bfhi(float x) {
    return __bfloat162float(__float2bfloat16(x));
}
__device__ __forceinline__ void ldsm4(uint32_t addr, uint32_t &r0, uint32_t &r1,
                                      uint32_t &r2, uint32_t &r3) {
    asm volatile("ldmatrix.sync.aligned.m8n8.x4.shared.b16 {%0,%1,%2,%3}, [%4];\n"
                 : "=r"(r0), "=r"(r1), "=r"(r2), "=r"(r3) : "r"(addr));
}
__device__ __forceinline__ void ldsm4t(uint32_t addr, uint32_t &r0, uint32_t &r1,
                                       uint32_t &r2, uint32_t &r3) {
    asm volatile("ldmatrix.sync.aligned.m8n8.x4.trans.shared.b16 {%0,%1,%2,%3}, [%4];\n"
                 : "=r"(r0), "=r"(r1), "=r"(r2), "=r"(r3) : "r"(addr));
}
__device__ __forceinline__ void mma16816(float d[4], uint32_t a0, uint32_t a1,
                                         uint32_t a2, uint32_t a3,
                                         uint32_t b0, uint32_t b1) {
    asm volatile("mma.sync.aligned.m16n8k16.row.col.f32.bf16.bf16.f32 "
                 "{%0,%1,%2,%3},{%4,%5,%6,%7},{%8,%9},{%0,%1,%2,%3};\n"
                 : "+f"(d[0]), "+f"(d[1]), "+f"(d[2]), "+f"(d[3])
                 : "r"(a0), "r"(a1), "r"(a2), "r"(a3), "r"(b0), "r"(b1));
}
// smem tile layout: rows of 64 bf16 = 128B, 8 chunks of 16B, chunk ^= (row&7)
__device__ __forceinline__ uint32_t laddr(uint32_t base, int row0, int chunk0,
                                          int lane) {
    int r = row0 + (lane & 15);
    int c = chunk0 + (lane >> 4);
    return base + (r << 7) + ((c ^ (r & 7)) << 4);
}
__device__ __forceinline__ void cpa16(uint32_t dst, const void* src) {
    asm volatile("cp.async.cg.shared.global [%0], [%1], 16;" :: "r"(dst), "l"(src) : "memory");
}
#define CPA_COMMIT()  asm volatile("cp.async.commit_group;" ::: "memory")
#define CPA_WAIT(n)   asm volatile("cp.async.wait_group %0;" :: "n"(n) : "memory")

// ---------------- RoPE table (double sincos, fast-math-proof) ---------------
__global__ void rope_table_kernel() {
    int idx = blockIdx.x * blockDim.x + threadIdx.x;
    if (idx >= SEQ*32) return;
    int s = idx >> 5, i = idx & 31;
    double invd = pow(10000.0, -((double)i) / 32.0);
    float ang = (float)s * (float)invd;
    double sv, cv;
    sincos((double)ang, &sv, &cv);
    g_cos[idx] = (float)cv;
    g_sin[idx] = (float)sv;
}

// ---------------- convert x + 4 weights to hi/lo planes ---------------------
__global__ void __launch_bounds__(256) convert_kernel(
    const float* __restrict__ x,  const float* __restrict__ wq,
    const float* __restrict__ wk, const float* __restrict__ wv,
    const float* __restrict__ wo)
{
    int idx = blockIdx.x * 256 + threadIdx.x;         // float4 index, 2M total
    const float* src; bf16 *dh, *dl; size_t off;
    if (idx < 1048576) {
        src = x + (size_t)idx*4; dh = g_xh; dl = g_xl; off = (size_t)idx*4;
    } else {
        int j = idx - 1048576;
        int w = j >> 18;                               // 256K float4 per weight
        int r = j & 262143;
        src = (w==0?wq : w==1?wk : w==2?wv : wo) + (size_t)r*4;
        dh = g_wwh; dl = g_wwl; off = (size_t)j*4;
    }
    float4 v = *(const float4*)src;
    float h0=bfhi(v.x), h1=bfhi(v.y), h2=bfhi(v.z), h3=bfhi(v.w);
    *(bf162*)(dh+off)   = __floats2bfloat162_rn(v.x, v.y);
    *(bf162*)(dh+off+2) = __floats2bfloat162_rn(v.z, v.w);
    *(bf162*)(dl+off)   = __floats2bfloat162_rn(v.x-h0, v.y-h1);
    *(bf162*)(dl+off+2) = __floats2bfloat162_rn(v.z-h2, v.w-h3);
}

// ============ plane GEMM: C[M,N] = A[M,K] * W[N,K]^T (split-3 bf16) =========
// CTA tile 256(M) x 128(N), BK=64, 256 threads, double-buffered cp.async.
// Warp w owns 32 M-rows (two 16-row groups sharing B fragments).
// Buffer layout: Ah(32K) Al(32K) Wh(16K) Wl(16K) = 96KB per buffer.
#define GEMM_SMEM (2*98304)    // 192KB

__global__ void __launch_bounds__(256, 1) gemm_pl_kernel(
    float* __restrict__ outp, int asel, int wsel, int dest_sel)
{
    extern __shared__ char sm[];
    uint32_t sbase = (uint32_t)__cvta_generic_to_shared(sm);
    const bf16* Ahp = asel ? g_ah : g_xh;
    const bf16* Alp = asel ? g_al : g_xl;
    const bf16* Whp = g_wwh + (size_t)wsel * HID * HID;
    const bf16* Wlp = g_wwl + (size_t)wsel * HID * HID;

    int tid = threadIdx.x, lane = tid & 31, wid = tid >> 5;
    int m0 = blockIdx.y << 8, n0 = blockIdx.x << 7;

    // ---- cp.async issue of one K-slab into buffer b ----
    // units: Ah rows 0..255 (2048), Al (2048), Wh rows 0..127 (1024), Wl (1024)
    auto issue = [&](int s, int b) {
        int k0 = s << 6;
        uint32_t bufb = sbase + b * 98304;
#pragma unroll
        for (int i = 0; i < 24; i++) {
            int g = (i << 8) + tid;                   // 0..6143
            const bf16* sp; int row; uint32_t pbase;
            if (g < 4096) {                            // A planes
                int plane = g >> 11;                   // 0 Ah, 1 Al
                int rem = g & 2047; row = rem >> 3;
                sp = plane ? Alp : Ahp;
                pbase = bufb + plane * 32768;
                int ch = rem & 7;
                const void* src = sp + (size_t)(m0 + row) * HID + k0 + ch * 8;
                cpa16(pbase + (row<<7) + ((ch ^ (row&7)) << 4), src);
            } else {                                   // W planes
                int g2 = g - 4096;
                int plane = g2 >> 10;                  // 0 Wh, 1 Wl
                int rem = g2 & 1023; row = rem >> 3;
                sp = plane ? Wlp : Whp;
                pbase = bufb + 65536 + plane * 16384;
                int ch = rem & 7;
                const void* src = sp + (size_t)(n0 + row) * HID + k0 + ch * 8;
                cpa16(pbase + (row<<7) + ((ch ^ (row&7)) << 4), src);
            }
        }
        CPA_COMMIT();
    };

    float acc[2][16][4];
#pragma unroll
    for (int rg = 0; rg < 2; rg++)
#pragma unroll
        for (int t = 0; t < 16; t++)
#pragma unroll
            for (int j = 0; j < 4; j++) acc[rg][t][j] = 0.f;

    issue(0, 0);
    for (int s = 0; s < 16; s++) {
        int bufi = s & 1;
        if (s + 1 < 16) { issue(s + 1, bufi ^ 1); CPA_WAIT(1); }
        else            { CPA_WAIT(0); }
        __syncthreads();
        uint32_t b0 = sbase + bufi * 98304;
        uint32_t uAh = b0, uAl = b0 + 32768, uWh = b0 + 65536, uWl = b0 + 81920;
#pragma unroll
        for (int ks = 0; ks < 4; ks++) {
            uint32_t ah[2][4], al[2][4];
#pragma unroll
            for (int rg = 0; rg < 2; rg++) {
                int r0w = 32*wid + 16*rg;
                ldsm4(laddr(uAh, r0w, 2*ks, lane), ah[rg][0],ah[rg][1],ah[rg][2],ah[rg][3]);
                ldsm4(laddr(uAl, r0w, 2*ks, lane), al[rg][0],al[rg][1],al[rg][2],al[rg][3]);
            }
#pragma unroll
            for (int p = 0; p < 8; p++) {
                uint32_t bh0,bh1,bh2,bh3, bl0,bl1,bl2,bl3;
                ldsm4(laddr(uWh, 16*p, 2*ks, lane), bh0,bh1,bh2,bh3);
                ldsm4(laddr(uWl, 16*p, 2*ks, lane), bl0,bl1,bl2,bl3);
#pragma unroll
                for (int rg = 0; rg < 2; rg++) {
                    mma16816(acc[rg][2*p],   ah[rg][0],ah[rg][1],ah[rg][2],ah[rg][3], bh0,bh2);
                    mma16816(acc[rg][2*p],   ah[rg][0],ah[rg][1],ah[rg][2],ah[rg][3], bl0,bl2);
                    mma16816(acc[rg][2*p],   al[rg][0],al[rg][1],al[rg][2],al[rg][3], bh0,bh2);
                    mma16816(acc[rg][2*p+1], ah[rg][0],ah[rg][1],ah[rg][2],ah[rg][3], bh1,bh3);
                    mma16816(acc[rg][2*p+1], ah[rg][0],ah[rg][1],ah[rg][2],ah[rg][3], bl1,bl3);
                    mma16816(acc[rg][2*p+1], al[rg][0],al[rg][1],al[rg][2],al[rg][3], bh1,bh3);
                }
            }
        }
        __syncthreads();
    }

    // ---- epilogue ----
    int cb = 2*(lane & 3);
#pragma unroll
    for (int rg = 0; rg < 2; rg++) {
        int r0 = m0 + 32*wid + 16*rg + (lane >> 2);
        if (dest_sel == 3) {
#pragma unroll
            for (int t = 0; t < 16; t++) {
                int col = n0 + 8*t + cb;
                *(float2*)(&outp[(size_t)r0 * HID + col])     = make_float2(acc[rg][t][0], acc[rg][t][1]);
                *(float2*)(&outp[(size_t)(r0+8) * HID + col]) = make_float2(acc[rg][t][2], acc[rg][t][3]);
            }
        } else {
            bf16 *dh, *dl;
            if      (dest_sel == 0) { dh = g_qh; dl = g_ql; }
            else if (dest_sel == 1) { dh = g_kh; dl = g_kl; }
            else                    { dh = g_vh; dl = g_vl; }
            float qs = (dest_sel == 0) ? 0.125f : 1.0f;
#pragma unroll
            for (int t = 0; t < 16; t++) {
                int col = n0 + 8*t + cb;                 // even
                int h = col >> 6, d = col & 63, d2 = d >> 1;
#pragma unroll
                for (int rr = 0; rr < 2; rr++) {
                    int row = r0 + rr*8;
                    int b = row >> 11, sq = row & (SEQ-1);
                    float v0 = acc[rg][t][rr*2], v1 = acc[rg][t][rr*2+1];
                    if (dest_sel < 2) {                  // RoPE
                        float c  = g_cos[(sq<<5) + d2];
                        float sn = g_sin[(sq<<5) + d2];
                        float o0 = v0*c - v1*sn;
                        float o1 = v0*sn + v1*c;
                        v0 = o0 * qs; v1 = o1 * qs;
                    }
                    size_t off = (((size_t)(b<<4) + h) * SEQ + sq) * HDIM + d;
                    float h0 = bfhi(v0), h1 = bfhi(v1);
                    *(bf162*)(dh + off) = __floats2bfloat162_rn(v0, v1);
                    *(bf162*)(dl + off) = __floats2bfloat162_rn(v0-h0, v1-h1);
                }
            }
        }
    }
}

// ============ plane flash attention (split-3 bf16 mma.sync) =================
// BQ=BK=128; 8 warps, warp w owns q-rows 16w..16w+15. Double-buffered K/V.
// smem: Qh(16K) Ql(16K) | 2 x [Kh Kl Vh Vl](64K) = 160KB
#define FLASH_SMEM (32768 + 2*65536)

__global__ void __launch_bounds__(256, 1) flash_pl_kernel() {
    extern __shared__ char smc[];
    uint32_t sbase = (uint32_t)__cvta_generic_to_shared(smc);
    int tid = threadIdx.x, lane = tid & 31, wid = tid >> 5;
    int bh = blockIdx.y;
    int q0 = blockIdx.x << 7;
    size_t hb = (size_t)bh * SEQ * HDIM;

    uint32_t uQh = sbase, uQl = sbase + 16384;

    // Q planes (group with tile 0)
    {
#pragma unroll
        for (int i = 0; i < 8; i++) {
            int g = (i << 8) + tid;
            int plane = g >> 10, rem = g & 1023, row = rem >> 3, ch = rem & 7;
            const bf16* sp = plane ? g_ql : g_qh;
            const void* src = sp + hb + (size_t)(q0 + row) * HDIM + ch * 8;
            uint32_t dst = sbase + plane*16384 + (row<<7) + ((ch ^ (row&7)) << 4);
            cpa16(dst, src);
        }
    }
    auto issue_kv = [&](int t, int b) {
        int kv = t << 7;
        uint32_t bufb = sbase + 32768 + b * 65536;
#pragma unroll
        for (int i = 0; i < 16; i++) {
            int g = (i << 8) + tid;
            int plane = g >> 10;                 // 0 Kh,1 Kl,2 Vh,3 Vl
            int rem = g & 1023, row = rem >> 3, ch = rem & 7;
            const bf16* sp = (plane==0) ? g_kh : (plane==1) ? g_kl
                           : (plane==2) ? g_vh : g_vl;
            const void* src = sp + hb + (size_t)(kv + row) * HDIM + ch * 8;
            uint32_t dst = bufb + plane*16384 + (row<<7) + ((ch ^ (row&7)) << 4);
            cpa16(dst, src);
        }
        CPA_COMMIT();
    };

    float o[8][4];
#pragma unroll
    for (int t = 0; t < 8; t++)
#pragma unroll
        for (int j = 0; j < 4; j++) o[t][j] = 0.f;
    float m0r = -INFINITY, m1r = -INFINITY, l0r = 0.f, l1r = 0.f;

    issue_kv(0, 0);   // commits Q + KV0 together
    for (int t = 0; t < 16; t++) {
        int bufi = t & 1;
        if (t + 1 < 16) { issue_kv(t + 1, bufi ^ 1); CPA_WAIT(1); }
        else            { CPA_WAIT(0); }
        __syncthreads();
        uint32_t b0 = sbase + 32768 + bufi * 65536;
        uint32_t uKh = b0, uKl = b0 + 16384, uVh = b0 + 32768, uVl = b0 + 49152;

        // ---- S = Q K^T ----
        float s[16][4];
#pragma unroll
        for (int tt = 0; tt < 16; tt++)
#pragma unroll
            for (int j = 0; j < 4; j++) s[tt][j] = 0.f;
#pragma unroll
        for (int ks = 0; ks < 4; ks++) {
            uint32_t ah0,ah1,ah2,ah3, al0,al1,al2,al3;
            ldsm4(laddr(uQh, 16*wid, 2*ks, lane), ah0,ah1,ah2,ah3);
            ldsm4(laddr(uQl, 16*wid, 2*ks, lane), al0,al1,al2,al3);
#pragma unroll
            for (int p = 0; p < 8; p++) {
                uint32_t bh0,bh1,bh2,bh3, bl0,bl1,bl2,bl3;
                ldsm4(laddr(uKh, 16*p, 2*ks, lane), bh0,bh1,bh2,bh3);
                ldsm4(laddr(uKl, 16*p, 2*ks, lane), bl0,bl1,bl2,bl3);
                mma16816(s[2*p],   ah0,ah1,ah2,ah3, bh0,bh2);
                mma16816(s[2*p],   ah0,ah1,ah2,ah3, bl0,bl2);
                mma16816(s[2*p],   al0,al1,al2,al3, bh0,bh2);
                mma16816(s[2*p+1], ah0,ah1,ah2,ah3, bh1,bh3);
                mma16816(s[2*p+1], ah0,ah1,ah2,ah3, bl1,bl3);
                mma16816(s[2*p+1], al0,al1,al2,al3, bh1,bh3);
            }
        }

        // ---- online softmax (row pairs live in quads) ----
        float mx0 = -INFINITY, mx1 = -INFINITY;
#pragma unroll
        for (int tt = 0; tt < 16; tt++) {
            mx0 = fmaxf(mx0, fmaxf(s[tt][0], s[tt][1]));
            mx1 = fmaxf(mx1, fmaxf(s[tt][2], s[tt][3]));
        }
        mx0 = fmaxf(mx0, __shfl_xor_sync(0xffffffffu, mx0, 1));
        mx0 = fmaxf(mx0, __shfl_xor_sync(0xffffffffu, mx0, 2));
        mx1 = fmaxf(mx1, __shfl_xor_sync(0xffffffffu, mx1, 1));
        mx1 = fmaxf(mx1, __shfl_xor_sync(0xffffffffu, mx1, 2));
        float nm0 = fmaxf(m0r, mx0), nm1 = fmaxf(m1r, mx1);
        float c0 = __expf(m0r - nm0), c1 = __expf(m1r - nm1);
        m0r = nm0; m1r = nm1;
        float sum0 = 0.f, sum1 = 0.f;
#pragma unroll
        for (int tt = 0; tt < 16; tt++) {
            s[tt][0] = __expf(s[tt][0] - nm0); sum0 += s[tt][0];
            s[tt][1] = __expf(s[tt][1] - nm0); sum0 += s[tt][1];
            s[tt][2] = __expf(s[tt][2] - nm1); sum1 += s[tt][2];
            s[tt][3] = __expf(s[tt][3] - nm1); sum1 += s[tt][3];
        }
        sum0 += __shfl_xor_sync(0xffffffffu, sum0, 1);
        sum0 += __shfl_xor_sync(0xffffffffu, sum0, 2);
        sum1 += __shfl_xor_sync(0xffffffffu, sum1, 1);
        sum1 += __shfl_xor_sync(0xffffffffu, sum1, 2);
        l0r = l0r * c0 + sum0;
        l1r = l1r * c1 + sum1;
#pragma unroll
        for (int tt = 0; tt < 8; tt++) {
            o[tt][0] *= c0; o[tt][1] *= c0; o[tt][2] *= c1; o[tt][3] *= c1;
        }

        // ---- O += P V (V via trans-ldmatrix on row-major planes) ----
#pragma unroll
        for (int km = 0; km < 8; km++) {
            int t0 = 2*km, t1 = t0 + 1;
            uint32_t a0h = pack2(s[t0][0], s[t0][1]);
            uint32_t a1h = pack2(s[t0][2], s[t0][3]);
            uint32_t a2h = pack2(s[t1][0], s[t1][1]);
            uint32_t a3h = pack2(s[t1][2], s[t1][3]);
            uint32_t a0l = pack2(s[t0][0]-bfhi(s[t0][0]), s[t0][1]-bfhi(s[t0][1]));
            uint32_t a1l = pack2(s[t0][2]-bfhi(s[t0][2]), s[t0][3]-bfhi(s[t0][3]));
            uint32_t a2l = pack2(s[t1][0]-bfhi(s[t1][0]), s[t1][1]-bfhi(s[t1][1]));
            uint32_t a3l = pack2(s[t1][2]-bfhi(s[t1][2]), s[t1][3]-bfhi(s[t1][3]));
#pragma unroll
            for (int p = 0; p < 4; p++) {
                uint32_t vh0,vh1,vh2,vh3, vl0,vl1,vl2,vl3;
                ldsm4t(laddr(uVh, 16*km, 2*p, lane), vh0,vh1,vh2,vh3);
                ldsm4t(laddr(uVl, 16*km, 2*p, lane), vl0,vl1,vl2,vl3);
                mma16816(o[2*p],   a0h,a1h,a2h,a3h, vh0,vh1);
                mma16816(o[2*p],   a0h,a1h,a2h,a3h, vl0,vl1);
                mma16816(o[2*p],   a0l,a1l,a2l,a3l, vh0,vh1);
                mma16816(o[2*p+1], a0h,a1h,a2h,a3h, vh2,vh3);
                mma16816(o[2*p+1], a0h,a1h,a2h,a3h, vl2,vl3);
                mma16816(o[2*p+1], a0l,a1l,a2l,a3l, vh2,vh3);
            }
        }
        __syncthreads();
    }

    // ---- epilogue: normalize, split to attn planes ----
    int b = bh >> 4, h = bh & 15;
    int r0 = q0 + 16*wid + (lane >> 2);
    float inv0 = 1.0f / l0r, inv1 = 1.0f / l1r;
#pragma unroll
    for (int t = 0; t < 8; t++) {
        int d = 8*t + 2*(lane & 3);
        size_t off0 = ((size_t)b * SEQ + r0)     * HID + (h<<6) + d;
        size_t off1 = ((size_t)b * SEQ + r0 + 8) * HID + (h<<6) + d;
        float v0 = o[t][0]*inv0, v1 = o[t][1]*inv0;
        float v2 = o[t][2]*inv1, v3 = o[t][3]*inv1;
        float h0=bfhi(v0), h1=bfhi(v1), h2=bfhi(v2), h3=bfhi(v3);
        *(bf162*)(g_ah + off0) = __floats2bfloat162_rn(v0, v1);
        *(bf162*)(g_al + off0) = __floats2bfloat162_rn(v0-h0, v1-h1);
        *(bf162*)(g_ah + off1) = __floats2bfloat162_rn(v2, v3);
        *(bf162*)(g_al + off1) = __floats2bfloat162_rn(v2-h2, v3-h3);
    }
}

// ---------------- launch ----------------------------------------------------
extern "C" void kernel_launch(void* const* d_in, const int* in_sizes, int n_in,
                              void* d_out, int out_size) {
    const float* x  = (const float*)d_in[0];
    const float* wq = (const float*)d_in[1];
    const float* wk = (const float*)d_in[2];
    const float* wv = (const float*)d_in[3];
    const float* wo = (const float*)d_in[4];
    float* out = (float*)d_out;

    cudaFuncSetAttribute(gemm_pl_kernel,
                         cudaFuncAttributeMaxDynamicSharedMemorySize, GEMM_SMEM);
    cudaFuncSetAttribute(flash_pl_kernel,
                         cudaFuncAttributeMaxDynamicSharedMemorySize, FLASH_SMEM);

    rope_table_kernel<<<(SEQ*32 + 255)/256, 256>>>();
    convert_kernel<<<8192, 256>>>(x, wq, wk, wv, wo);

    dim3 gg(HID/128, NTOK/256);                 // (8, 16) = 128 CTAs, 1 wave
    gemm_pl_kernel<<<gg, 256, GEMM_SMEM>>>(nullptr, 0, 0, 0);  // q (+rope, scaled)
    gemm_pl_kernel<<<gg, 256, GEMM_SMEM>>>(nullptr, 0, 1, 1);  // k (+rope)
    gemm_pl_kernel<<<gg, 256, GEMM_SMEM>>>(nullptr, 0, 2, 2);  // v

    dim3 fg(SEQ/128, BATCH*NHEADS);             // (16, 32)
    flash_pl_kernel<<<fg, 256, FLASH_SMEM>>>();

    gemm_pl_kernel<<<gg, 256, GEMM_SMEM>>>(out, 1, 3, 3);      // attn * wo
}